// round 15
// baseline (speedup 1.0000x reference)
#include <cuda_runtime.h>
#include <cuda_bf16.h>
#include <stdint.h>

#define BATCH   2
#define SEQ     2048
#define DMODEL  1024
#define NHEADS  16
#define DK      64
#define MROWS   (BATCH*SEQ)      // 4096
typedef __nv_bfloat16  bf16;
typedef __nv_bfloat162 bf162;

// ---- scratch (__device__ globals: allocation-free rule) ----
__device__ bf16 g_Aqh[MROWS*DMODEL], g_Aql[MROWS*DMODEL];
__device__ bf16 g_Akh[MROWS*DMODEL], g_Akl[MROWS*DMODEL];
__device__ bf16 g_Avh[MROWS*DMODEL], g_Avl[MROWS*DMODEL];
__device__ bf16 g_Wqh[DMODEL*DMODEL], g_Wql[DMODEL*DMODEL];
__device__ bf16 g_Wkh[DMODEL*DMODEL], g_Wkl[DMODEL*DMODEL];
__device__ bf16 g_Wvh[DMODEL*DMODEL], g_Wvl[DMODEL*DMODEL];
__device__ bf16 g_Woh[DMODEL*DMODEL], g_Wol[DMODEL*DMODEL];
__device__ bf16 g_Qh[MROWS*DMODEL], g_Ql[MROWS*DMODEL];
__device__ bf16 g_Kh[MROWS*DMODEL], g_Kl[MROWS*DMODEL];
__device__ bf16 g_Vh[MROWS*DMODEL], g_Vl[MROWS*DMODEL];
__device__ bf16 g_Ch[MROWS*DMODEL], g_Cl[MROWS*DMODEL];

__device__ __forceinline__ uint32_t smem_u32(const void* p) {
    uint32_t a;
    asm("{ .reg .u64 t; cvta.to.shared.u64 t, %1; cvt.u32.u64 %0, t; }" : "=r"(a) : "l"(p));
    return a;
}

#define LDSM4(r, addr) asm volatile( \
    "ldmatrix.sync.aligned.m8n8.x4.shared.b16 {%0,%1,%2,%3}, [%4];" \
    : "=r"((r)[0]), "=r"((r)[1]), "=r"((r)[2]), "=r"((r)[3]) : "r"(addr))

#define LDSM4_T(r, addr) asm volatile( \
    "ldmatrix.sync.aligned.m8n8.x4.trans.shared.b16 {%0,%1,%2,%3}, [%4];" \
    : "=r"((r)[0]), "=r"((r)[1]), "=r"((r)[2]), "=r"((r)[3]) : "r"(addr))

#define MMA_BF16(d, a, b) asm volatile( \
    "mma.sync.aligned.m16n8k16.row.col.f32.bf16.bf16.f32 " \
    "{%0,%1,%2,%3}, {%4,%5,%6,%7}, {%8,%9}, {%0,%1,%2,%3};" \
    : "+f"((d)[0]), "+f"((d)[1]), "+f"((d)[2]), "+f"((d)[3]) \
    : "r"((a)[0]), "r"((a)[1]), "r"((a)[2]), "r"((a)[3]), "r"((b)[0]), "r"((b)[1]))

__device__ __forceinline__ void cp16(uint32_t saddr, const void* g) {
    asm volatile("cp.async.cg.shared.global [%0], [%1], 16;" :: "r"(saddr), "l"(g));
}
#define CP_COMMIT() asm volatile("cp.async.commit_group;" ::: "memory")
#define CP_WAIT1()  asm volatile("cp.async.wait_group 1;" ::: "memory")
#define CP_WAIT0()  asm volatile("cp.async.wait_group 0;" ::: "memory")

// 128B-row swizzled tile: byte offset of (row, kb bytes within 128B row)
__device__ __forceinline__ uint32_t off128(int row, int kb) {
    return row * 128 + ((((kb >> 4) ^ (row & 7)) & 7) << 4) + (kb & 15);
}

__device__ __forceinline__ void split_bf(float v, bf16& h, bf16& l) {
    h = __float2bfloat16(v);
    l = __float2bfloat16(v - __bfloat162float(h));
}

// MUFU exp2 (rare uses: per-row rescale, fac tables). ex2(-1e30) -> 0.
__device__ __forceinline__ float ex2a(float x) {
    float r;
    asm("ex2.approx.f32 %0, %1;" : "=f"(r) : "f"(x));
    return r;
}

// FMA-pipe exp2 for the bulk softmax (x <= 0). Degree-5 Taylor on [-.5,.5],
// rel err ~2.4e-6, exactly 1 at x=0. ~11 ops on fma/alu pipes (128/cyc/SM)
// vs 1 MUFU op (4/cyc/SM) -> ~3x phase throughput.
__device__ __forceinline__ float fexp2(float x) {
    x = fmaxf(x, -126.f);
    float n = rintf(x);
    float f = x - n;
    float p = 1.33336e-3f;
    p = fmaf(p, f, 9.61813e-3f);
    p = fmaf(p, f, 5.55041e-2f);
    p = fmaf(p, f, 2.40226507e-1f);
    p = fmaf(p, f, 6.93147181e-1f);
    p = fmaf(p, f, 1.0f);
    float s = __int_as_float(((int)n + 127) << 23);
    return p * s;
}

// ---------------------------------------------------------------------------
// cvt7: split 7 fp32 tensors (q,k,v 4M; wq,wk,wv,wo 1M) into bf16 hi/lo.
// ---------------------------------------------------------------------------
__global__ __launch_bounds__(256) void cvt7(
    const float* x0, const float* x1, const float* x2, const float* x3,
    const float* x4, const float* x5, const float* x6,
    bf16* h0, bf16* h1, bf16* h2, bf16* h3, bf16* h4, bf16* h5, bf16* h6,
    bf16* l0, bf16* l1, bf16* l2, bf16* l3, bf16* l4, bf16* l5, bf16* l6)
{
    const float* xs[7] = {x0, x1, x2, x3, x4, x5, x6};
    bf16* hs[7] = {h0, h1, h2, h3, h4, h5, h6};
    bf16* ls[7] = {l0, l1, l2, l3, l4, l5, l6};
    int t = blockIdx.y;
    int n = (t < 3) ? MROWS * DMODEL : DMODEL * DMODEL;
    int i = (blockIdx.x * 256 + threadIdx.x) * 4;
    if (i >= n) return;
    float4 v = *(const float4*)(xs[t] + i);
    bf16 a, b, c, d, e, f, g, h;
    split_bf(v.x, a, e); split_bf(v.y, b, f);
    split_bf(v.z, c, g); split_bf(v.w, d, h);
    *(bf162*)(hs[t] + i)     = __halves2bfloat162(a, b);
    *(bf162*)(hs[t] + i + 2) = __halves2bfloat162(c, d);
    *(bf162*)(ls[t] + i)     = __halves2bfloat162(e, f);
    *(bf162*)(ls[t] + i + 2) = __halves2bfloat162(g, h);
}

// ---------------------------------------------------------------------------
// mma.sync GEMM: 3-pass split-bf16, 2-stage cp.async. Output either fp32
// (C != null) or split bf16 (Chi/Clo).
// ---------------------------------------------------------------------------
#define STG       65536
#define GEMM_SMEM (2*STG)

__global__ __launch_bounds__(256) void gemm_mma(
    const bf16* __restrict__ Ahi, const bf16* __restrict__ Alo,
    const bf16* __restrict__ Whi, const bf16* __restrict__ Wlo,
    const float* __restrict__ bias, float* __restrict__ C,
    bf16* __restrict__ Chi, bf16* __restrict__ Clo,
    int M, int N, int K)
{
    extern __shared__ char sm[];
    const uint32_t sb = smem_u32(sm);
    const int tid = threadIdx.x, lane = tid & 31, wid = tid >> 5;
    const int wm = (wid >> 2) * 64, wn = (wid & 3) * 32;
    const int bm = blockIdx.y * 128, bn = blockIdx.x * 128;
    const int aRow = lane & 15,                       aKb = (lane >> 4) * 16;
    const int bRow = (lane & 7) + ((lane >> 4) << 3), bKb = ((lane >> 3) & 1) * 16;

    float acc[4][4][4];
#pragma unroll
    for (int i = 0; i < 4; i++)
#pragma unroll
        for (int j = 0; j < 4; j++)
#pragma unroll
            for (int r = 0; r < 4; r++) acc[i][j][r] = 0.f;

    const int nCh = K / 64;
    auto load_chunk = [&](int ch, int st) {
        const int k0 = ch * 64;
        const uint32_t stg = sb + st * STG;
#pragma unroll
        for (int s = 0; s < 4; s++) {
            int idx = tid + s * 256;
            int r = idx >> 3, g = idx & 7;
            uint32_t so = r * 128 + ((g ^ (r & 7)) << 4);
            const size_t ga = (size_t)(bm + r) * K + k0 + g * 8;
            const size_t gb = (size_t)(bn + r) * K + k0 + g * 8;
            cp16(stg + so,         Ahi + ga);
            cp16(stg + 16384 + so, Alo + ga);
            cp16(stg + 32768 + so, Whi + gb);
            cp16(stg + 49152 + so, Wlo + gb);
        }
        CP_COMMIT();
    };

    load_chunk(0, 0);
    for (int ch = 0; ch < nCh; ch++) {
        if (ch + 1 < nCh) { load_chunk(ch + 1, (ch + 1) & 1); CP_WAIT1(); }
        else              { CP_WAIT0(); }
        __syncthreads();
        const uint32_t stg  = sb + (ch & 1) * STG;
        const uint32_t sAhi = stg, sAlo = stg + 16384;
        const uint32_t sBhi = stg + 32768, sBlo = stg + 49152;
#pragma unroll
        for (int ks = 0; ks < 4; ks++) {
            const int kb = ks * 32;
            uint32_t ah[4][4], bh[2][4];
#pragma unroll
            for (int mt = 0; mt < 4; mt++)
                LDSM4(ah[mt], sAhi + off128(wm + mt * 16 + aRow, kb + aKb));
#pragma unroll
            for (int n2 = 0; n2 < 2; n2++)
                LDSM4(bh[n2], sBhi + off128(wn + n2 * 16 + bRow, kb + bKb));
#pragma unroll
            for (int mt = 0; mt < 4; mt++)
#pragma unroll
                for (int nt = 0; nt < 4; nt++)
                    MMA_BF16(acc[mt][nt], ah[mt], &bh[nt >> 1][(nt & 1) * 2]);
            uint32_t al[4][4];
#pragma unroll
            for (int mt = 0; mt < 4; mt++)
                LDSM4(al[mt], sAlo + off128(wm + mt * 16 + aRow, kb + aKb));
#pragma unroll
            for (int mt = 0; mt < 4; mt++)
#pragma unroll
                for (int nt = 0; nt < 4; nt++)
                    MMA_BF16(acc[mt][nt], al[mt], &bh[nt >> 1][(nt & 1) * 2]);
            uint32_t bl[2][4];
#pragma unroll
            for (int n2 = 0; n2 < 2; n2++)
                LDSM4(bl[n2], sBlo + off128(wn + n2 * 16 + bRow, kb + bKb));
#pragma unroll
            for (int mt = 0; mt < 4; mt++)
#pragma unroll
                for (int nt = 0; nt < 4; nt++)
                    MMA_BF16(acc[mt][nt], ah[mt], &bl[nt >> 1][(nt & 1) * 2]);
        }
        __syncthreads();
    }

    const int r0 = lane >> 2, c0 = (lane & 3) * 2;
#pragma unroll
    for (int mt = 0; mt < 4; mt++) {
        int m0 = bm + wm + mt * 16 + r0;
#pragma unroll
        for (int nt = 0; nt < 4; nt++) {
            int n = bn + wn + nt * 8 + c0;
            float b0 = bias[n], b1 = bias[n + 1];
            float v00 = acc[mt][nt][0] + b0, v01 = acc[mt][nt][1] + b1;
            float v10 = acc[mt][nt][2] + b0, v11 = acc[mt][nt][3] + b1;
            if (C) {
                *(float2*)&C[(size_t)m0 * N + n] = {v00, v01};
                *(float2*)&C[(size_t)(m0 + 8) * N + n] = {v10, v11};
            } else {
                bf16 h0, l0, h1, l1;
                split_bf(v00, h0, l0); split_bf(v01, h1, l1);
                *(bf162*)&Chi[(size_t)m0 * N + n] = __halves2bfloat162(h0, h1);
                *(bf162*)&Clo[(size_t)m0 * N + n] = __halves2bfloat162(l0, l1);
                split_bf(v10, h0, l0); split_bf(v11, h1, l1);
                *(bf162*)&Chi[(size_t)(m0 + 8) * N + n] = __halves2bfloat162(h0, h1);
                *(bf162*)&Clo[(size_t)(m0 + 8) * N + n] = __halves2bfloat162(l0, l1);
            }
        }
    }
}

// ---------------------------------------------------------------------------
// Fused flash-style attention, all-MMA, split-bf16, exp2-space softmax.
// scale folded with log2e; bulk exp on FMA pipe (fexp2), rare exps on MUFU.
// V natural layout + ldmatrix.trans for P@V. K region reused for P.
// ---------------------------------------------------------------------------
#define QHI   0
#define QLO   16384
#define PHI   32768        // K hi/lo alias the P region (dead by P-write time)
#define KHI   32768
#define KLO   40960
#define PLO   49152
#define VHI   65536        // V natural [64 kv][64 dk] hi
#define VLO   73728        // V natural lo
#define SNM   81920        // 32*128 floats
#define SRA   98304        // 4*128 floats
#define SRB   100352       // 4*128 floats
#define SML   102400       // 128 float2
#define ATTN_SMEM 103424

__global__ __launch_bounds__(256, 2) void attn_mma(
    const bf16* __restrict__ Qh, const bf16* __restrict__ Ql,
    const bf16* __restrict__ Kh, const bf16* __restrict__ Kl,
    const bf16* __restrict__ Vh, const bf16* __restrict__ Vl,
    float* __restrict__ attn, bf16* __restrict__ Ch, bf16* __restrict__ Cl)
{
    extern __shared__ char sm[];
    const uint32_t sb = smem_u32(sm);
    float* sNM  = (float*)(sm + SNM);
    float* sRA  = (float*)(sm + SRA);
    float* sRB  = (float*)(sm + SRB);
    float2* sML = (float2*)(sm + SML);

    const int b = blockIdx.z, h = blockIdx.y, q0 = blockIdx.x * 128;
    const int tid = threadIdx.x, lane = tid & 31, wid = tid >> 5;
    const int wq = wid >> 2, wk4 = wid & 3;      // wk4: kv-warp (QK) / dk-warp (PV)
    const int r0 = lane >> 2, c0 = (lane & 3) * 2;
    const int aRow = lane & 15,                       aKb = (lane >> 4) * 16;
    const int bRow = (lane & 7) + ((lane >> 4) << 3), bKb = ((lane >> 3) & 1) * 16;
    // trans-ldmatrix lane geometry for V^T fragments
    const int vRow8 = ((lane >> 3) & 1) * 8 + (lane & 7);      // kv within 16-chunk
    const int vColB = (wk4 * 16 + ((lane >> 4) << 3)) * 2;     // dk byte offset
    const float scale2 = 0.18033688f;   // (1/8) * log2(e): exp2-space scores

    const size_t rowQ0 = (size_t)b * SEQ + q0;
    const int hoff = h * DK;
    float* attnB = attn + ((size_t)(b * NHEADS + h)) * SEQ * SEQ;

    // Load Q tile (hi/lo) [128 q][64 dk]
    for (int s = 0; s < 4; s++) {
        int idx = tid + s * 256;                 // 1024 uint4 per buffer
        int r = idx >> 3, g = idx & 7;
        uint32_t so = off128(r, g * 16);
        cp16(sb + QHI + so, &Qh[(rowQ0 + r) * DMODEL + hoff + g * 8]);
        cp16(sb + QLO + so, &Ql[(rowQ0 + r) * DMODEL + hoff + g * 8]);
    }
    CP_COMMIT();

    float m[8], l[8], acc_o[4][2][4];
#pragma unroll
    for (int i = 0; i < 8; i++) { m[i] = -1e30f; l[i] = 0.f; }
#pragma unroll
    for (int i = 0; i < 4; i++)
#pragma unroll
        for (int j = 0; j < 2; j++)
#pragma unroll
            for (int r = 0; r < 4; r++) acc_o[i][j][r] = 0.f;

    for (int kt = 0; kt < 32; kt++) {
        // K tile [64 kv][64 dk] + V tile [64 kv][64 dk], both natural layout
        for (int s = 0; s < 2; s++) {
            int idx = tid + s * 256;             // 512 uint4 per buffer
            int r = idx >> 3, g = idx & 7;
            uint32_t so = off128(r, g * 16);
            size_t gr = ((size_t)b * SEQ + kt * 64 + r) * DMODEL + hoff + g * 8;
            cp16(sb + KHI + so, &Kh[gr]);
            cp16(sb + KLO + so, &Kl[gr]);
            cp16(sb + VHI + so, &Vh[gr]);
            cp16(sb + VLO + so, &Vl[gr]);
        }
        CP_COMMIT();
        CP_WAIT0();
        __syncthreads();

        // S = Q @ K^T (3 passes), exp2-space
        float acc[4][2][4];
#pragma unroll
        for (int i = 0; i < 4; i++)
#pragma unroll
            for (int j = 0; j < 2; j++)
#pragma unroll
                for (int r = 0; r < 4; r++) acc[i][j][r] = 0.f;
#pragma unroll
        for (int ks = 0; ks < 4; ks++) {
            const int kb = ks * 32;
            uint32_t ah[4][4], bh[4], al[4][4], bl[4];
#pragma unroll
            for (int mt = 0; mt < 4; mt++)
                LDSM4(ah[mt], sb + QHI + off128(wq * 64 + mt * 16 + aRow, kb + aKb));
            LDSM4(bh, sb + KHI + off128(wk4 * 16 + bRow, kb + bKb));
#pragma unroll
            for (int mt = 0; mt < 4; mt++)
#pragma unroll
                for (int nt = 0; nt < 2; nt++)
                    MMA_BF16(acc[mt][nt], ah[mt], &bh[nt * 2]);
#pragma unroll
            for (int mt = 0; mt < 4; mt++)
                LDSM4(al[mt], sb + QLO + off128(wq * 64 + mt * 16 + aRow, kb + aKb));
#pragma unroll
            for (int mt = 0; mt < 4; mt++)
#pragma unroll
                for (int nt = 0; nt < 2; nt++)
                    MMA_BF16(acc[mt][nt], al[mt], &bh[nt * 2]);
            LDSM4(bl, sb + KLO + off128(wk4 * 16 + bRow, kb + bKb));
#pragma unroll
            for (int mt = 0; mt < 4; mt++)
#pragma unroll
                for (int nt = 0; nt < 2; nt++)
                    MMA_BF16(acc[mt][nt], ah[mt], &bl[nt * 2]);
        }

        // scale + warp-local row max -> sRA
#pragma unroll
        for (int mt = 0; mt < 4; mt++)
#pragma unroll
            for (int h2 = 0; h2 < 2; h2++) {
                float v = -1e30f;
#pragma unroll
                for (int nt = 0; nt < 2; nt++)
#pragma unroll
                    for (int j = 0; j < 2; j++) {
                        acc[mt][nt][h2 * 2 + j] *= scale2;
                        v = fmaxf(v, acc[mt][nt][h2 * 2 + j]);
                    }
                v = fmaxf(v, __shfl_xor_sync(~0u, v, 1));
                v = fmaxf(v, __shfl_xor_sync(~0u, v, 2));
                if ((lane & 3) == 0)
                    sRA[wk4 * 128 + wq * 64 + mt * 16 + h2 * 8 + r0] = v;
            }
        __syncthreads();   // all QK MMA done; K dead; sRA complete

        // softmax: fexp2 (FMA pipe), p' out, split-bf16 P, partial sums
#pragma unroll
        for (int mt = 0; mt < 4; mt++)
#pragma unroll
            for (int h2 = 0; h2 < 2; h2++) {
                int s = mt * 2 + h2;
                int rowL = wq * 64 + mt * 16 + h2 * 8 + r0;
                float tmax = fmaxf(fmaxf(sRA[rowL], sRA[128 + rowL]),
                                   fmaxf(sRA[256 + rowL], sRA[384 + rowL]));
                float nm = fmaxf(m[s], tmax);
                float resc = ex2a(m[s] - nm);
                float sum = 0.f;
#pragma unroll
                for (int nt = 0; nt < 2; nt++) {
                    float p0 = fexp2(acc[mt][nt][h2 * 2 + 0] - nm);
                    float p1 = fexp2(acc[mt][nt][h2 * 2 + 1] - nm);
                    sum += p0 + p1;
                    int col = wk4 * 16 + nt * 8 + c0;
                    *(float2*)&attnB[(size_t)(q0 + rowL) * SEQ + kt * 64 + col] = {p0, p1};
                    bf16 ph0, pl0, ph1, pl1;
                    split_bf(p0, ph0, pl0); split_bf(p1, ph1, pl1);
                    *(bf162*)(sm + PHI + off128(rowL, col * 2)) = __halves2bfloat162(ph0, ph1);
                    *(bf162*)(sm + PLO + off128(rowL, col * 2)) = __halves2bfloat162(pl0, pl1);
                }
                sum += __shfl_xor_sync(~0u, sum, 1);
                sum += __shfl_xor_sync(~0u, sum, 2);
                if ((lane & 3) == 0) sRB[wk4 * 128 + rowL] = sum;
                // rescale O accumulators
#pragma unroll
                for (int nt = 0; nt < 2; nt++)
#pragma unroll
                    for (int j = 0; j < 2; j++) acc_o[mt][nt][h2 * 2 + j] *= resc;
                l[s] *= resc;
                m[s] = nm;
                if (wk4 == 0 && (lane & 3) == 0) sNM[kt * 128 + rowL] = nm;
            }
        __syncthreads();   // P, sRB complete

        // finish l with cross-warp sums
#pragma unroll
        for (int mt = 0; mt < 4; mt++)
#pragma unroll
            for (int h2 = 0; h2 < 2; h2++) {
                int rowL = wq * 64 + mt * 16 + h2 * 8 + r0;
                l[mt * 2 + h2] += sRB[rowL] + sRB[128 + rowL] + sRB[256 + rowL] + sRB[384 + rowL];
            }

        // O += P @ V (3 passes). B-operand = V^T via ldmatrix.trans.
#pragma unroll
        for (int ks = 0; ks < 4; ks++) {
            const int kb = ks * 32;
            uint32_t ap[4][4], bp[4], al2[4][4], bl2[4];
#pragma unroll
            for (int mt = 0; mt < 4; mt++)
                LDSM4(ap[mt], sb + PHI + off128(wq * 64 + mt * 16 + aRow, kb + aKb));
            LDSM4_T(bp, sb + VHI + off128(ks * 16 + vRow8, vColB));
#pragma unroll
            for (int mt = 0; mt < 4; mt++)
#pragma unroll
                for (int nt = 0; nt < 2; nt++)
                    MMA_BF16(acc_o[mt][nt], ap[mt], &bp[nt * 2]);
#pragma unroll
            for (int mt = 0; mt < 4; mt++)
                LDSM4(al2[mt], sb + PLO + off128(wq * 64 + mt * 16 + aRow, kb + aKb));
#pragma unroll
            for (int mt = 0; mt < 4; mt++)
#pragma unroll
                for (int nt = 0; nt < 2; nt++)
                    MMA_BF16(acc_o[mt][nt], al2[mt], &bp[nt * 2]);
            LDSM4_T(bl2, sb + VLO + off128(ks * 16 + vRow8, vColB));
#pragma unroll
            for (int mt = 0; mt < 4; mt++)
#pragma unroll
                for (int nt = 0; nt < 2; nt++)
                    MMA_BF16(acc_o[mt][nt], ap[mt], &bl2[nt * 2]);
        }
        __syncthreads();   // PV done before next tile overwrites K/P and V
    }

    // ctx = O / l, split bf16
#pragma unroll
    for (int mt = 0; mt < 4; mt++)
#pragma unroll
        for (int h2 = 0; h2 < 2; h2++) {
            int s = mt * 2 + h2;
            float il = 1.f / l[s];
            int rowL = wq * 64 + mt * 16 + h2 * 8 + r0;
#pragma unroll
            for (int nt = 0; nt < 2; nt++) {
                float v0 = acc_o[mt][nt][h2 * 2 + 0] * il;
                float v1 = acc_o[mt][nt][h2 * 2 + 1] * il;
                bf16 h0, l0, h1, l1;
                split_bf(v0, h0, l0); split_bf(v1, h1, l1);
                size_t go = (rowQ0 + rowL) * DMODEL + hoff + wk4 * 16 + nt * 8 + c0;
                *(bf162*)&Ch[go] = __halves2bfloat162(h0, h1);
                *(bf162*)&Cl[go] = __halves2bfloat162(l0, l1);
            }
            if (wk4 == 0 && (lane & 3) == 0) sML[rowL] = {m[s], 1.f / l[s]};
        }
    __syncthreads();
    // fac table: sNM <- 2^(nm - m_final) / l
    for (int i = tid; i < 32 * 128; i += 256) {
        int row = i & 127;
        float2 ml = sML[row];
        sNM[i] = ex2a(sNM[i] - ml.x) * ml.y;
    }
    __syncthreads();
    // normalize sweep: P = p' * fac
    for (int i = tid; i < 128 * 512; i += 256) {
        int row = i >> 9, f4 = i & 511;
        float fac = sNM[((f4 >> 4) << 7) + row];
        float4* gp = (float4*)&attnB[(size_t)(q0 + row) * SEQ + f4 * 4];
        float4 v = *gp;
        v.x *= fac; v.y *= fac; v.z *= fac; v.w *= fac;
        *gp = v;
    }
}

// ---------------------------------------------------------------------------
extern "C" void kernel_launch(void* const* d_in, const int* in_sizes, int n_in,
                              void* d_out, int out_size)
{
    const float* q  = (const float*)d_in[0];
    const float* k  = (const float*)d_in[1];
    const float* v  = (const float*)d_in[2];
    const float* wq = (const float*)d_in[3];
    const float* bq = (const float*)d_in[4];
    const float* wk = (const float*)d_in[5];
    const float* bk = (const float*)d_in[6];
    const float* wv = (const float*)d_in[7];
    const float* bv = (const float*)d_in[8];
    const float* wo = (const float*)d_in[9];
    const float* bo = (const float*)d_in[10];

    float* out  = (float*)d_out;
    float* attn = out + (size_t)MROWS * DMODEL;

    bf16 *Aqh, *Aql, *Akh, *Akl, *Avh, *Avl;
    bf16 *Wqh, *Wql, *Wkh, *Wkl, *Wvh, *Wvl, *Woh, *Wol;
    bf16 *Qh, *Ql, *Kh, *Kl, *Vh, *Vl, *Ch, *Cl;
    cudaGetSymbolAddress((void**)&Aqh, g_Aqh); cudaGetSymbolAddress((void**)&Aql, g_Aql);
    cudaGetSymbolAddress((void**)&Akh, g_Akh); cudaGetSymbolAddress((void**)&Akl, g_Akl);
    cudaGetSymbolAddress((void**)&Avh, g_Avh); cudaGetSymbolAddress((void**)&Avl, g_Avl);
    cudaGetSymbolAddress((void**)&Wqh, g_Wqh); cudaGetSymbolAddress((void**)&Wql, g_Wql);
    cudaGetSymbolAddress((void**)&Wkh, g_Wkh); cudaGetSymbolAddress((void**)&Wkl, g_Wkl);
    cudaGetSymbolAddress((void**)&Wvh, g_Wvh); cudaGetSymbolAddress((void**)&Wvl, g_Wvl);
    cudaGetSymbolAddress((void**)&Woh, g_Woh); cudaGetSymbolAddress((void**)&Wol, g_Wol);
    cudaGetSymbolAddress((void**)&Qh, g_Qh);   cudaGetSymbolAddress((void**)&Ql, g_Ql);
    cudaGetSymbolAddress((void**)&Kh, g_Kh);   cudaGetSymbolAddress((void**)&Kl, g_Kl);
    cudaGetSymbolAddress((void**)&Vh, g_Vh);   cudaGetSymbolAddress((void**)&Vl, g_Vl);
    cudaGetSymbolAddress((void**)&Ch, g_Ch);   cudaGetSymbolAddress((void**)&Cl, g_Cl);

    static int attr_set = 0;
    if (!attr_set) {
        cudaFuncSetAttribute(gemm_mma, cudaFuncAttributeMaxDynamicSharedMemorySize, GEMM_SMEM);
        cudaFuncSetAttribute(attn_mma, cudaFuncAttributeMaxDynamicSharedMemorySize, ATTN_SMEM);
        attr_set = 1;
    }

    dim3 ggrid(DMODEL / 128, MROWS / 128); // (8, 32)

    cvt7<<<dim3(MROWS * DMODEL / 1024, 7), 256>>>(
        q, k, v, wq, wk, wv, wo,
        Aqh, Akh, Avh, Wqh, Wkh, Wvh, Woh,
        Aql, Akl, Avl, Wql, Wkl, Wvl, Wol);                               // 0

    gemm_mma<<<ggrid, 256, GEMM_SMEM>>>(Aqh, Aql, Wqh, Wql, bq,
        nullptr, Qh, Ql, MROWS, DMODEL, DMODEL);                          // 1
    gemm_mma<<<ggrid, 256, GEMM_SMEM>>>(Akh, Akl, Wkh, Wkl, bk,
        nullptr, Kh, Kl, MROWS, DMODEL, DMODEL);                          // 2
    gemm_mma<<<ggrid, 256, GEMM_SMEM>>>(Avh, Avl, Wvh, Wvl, bv,
        nullptr, Vh, Vl, MROWS, DMODEL, DMODEL);                          // 3

    attn_mma<<<dim3(SEQ / 128, NHEADS, BATCH), 256, ATTN_SMEM>>>(
        Qh, Ql, Kh, Kl, Vh, Vl, attn, Ch, Cl);                            // 4

    gemm_mma<<<ggrid, 256, GEMM_SMEM>>>(Ch, Cl, Woh, Wol, bo,
        out, nullptr, nullptr, MROWS, DMODEL, DMODEL);                    // 5
}